// round 16
// baseline (speedup 1.0000x reference)
#include <cuda_runtime.h>
#include <cuda_fp16.h>

#define NN 50000
#define NE 800000
#define HN 25000          // node pairs: pair p handles nodes p and p+HN
#define PREP0_BLOCKS 196  // ceil(25000/128) prep blocks inside fused kernel
#define HIST_BLOCKS 3125  // 800000/256
#define NB 3125           // buckets: src>>4 (16 nodes/bucket)

// Scratch (device globals — no allocation allowed in kernel_launch).
__device__ float4 g_Z4[(size_t)NN * 20];      // per-node Z, fp16, 320B stride
__device__ float  g_agg[2][(size_t)NN * 16];  // ping-pong node feature buffers
// bucket-sorted edge arrays (rebuilt every launch):
__device__ float4 g_spc[(size_t)NE * 2];      // packed broadcast fp16 coeffs
__device__ int2   g_sidx[(size_t)NE];         // (src, dst), bucket-ordered by src>>4
// bucket-sort scratch. g_cnt INVARIANT: zero at every kernel_launch entry
// (zero-initialized at module load; scan_kernel re-zeroes after reading).
__device__ int g_cnt[NB];
__device__ int g_cur[NB];

// ---- packed f32x2 helpers (FFMA2: 2 fp32 FMAs per instruction, exact) ----
__device__ __forceinline__ unsigned long long f2pack(float lo, float hi) {
    unsigned long long d;
    asm("mov.b64 %0, {%1, %2};" : "=l"(d) : "f"(lo), "f"(hi));
    return d;
}
__device__ __forceinline__ void f2unpack(unsigned long long v, float& lo, float& hi) {
    asm("mov.b64 {%0, %1}, %2;" : "=f"(lo), "=f"(hi) : "l"(v));
}
__device__ __forceinline__ unsigned long long ffma2(
    unsigned long long a, unsigned long long b, unsigned long long c) {
    unsigned long long d;
    asm("fma.rn.f32x2 %0, %1, %2, %3;" : "=l"(d) : "l"(a), "l"(b), "l"(c));
    return d;
}

// ---------------------------------------------------------------------------
// Core prep math for one pair (n0, n1): Z rows [d0,d1) + optional root term.
// ---------------------------------------------------------------------------
__device__ __forceinline__ void prep_pair(
    const float* __restrict__ xin, int n0, int n1, int r, bool relu,
    const float4* sWB, const float4* sR, const float4* sBias, float* aggOut)
{
    unsigned long long xa[16], xb[16];
    {
        const float4* xr0 = (const float4*)(xin + (size_t)n0 * 16);
        const float4* xr1 = (const float4*)(xin + (size_t)n1 * 16);
        #pragma unroll
        for (int cc = 0; cc < 4; cc++) {
            float4 v0 = xr0[cc];
            float4 v1 = xr1[cc];
            if (relu) {
                v0.x = fmaxf(v0.x, 0.f); v0.y = fmaxf(v0.y, 0.f);
                v0.z = fmaxf(v0.z, 0.f); v0.w = fmaxf(v0.w, 0.f);
                v1.x = fmaxf(v1.x, 0.f); v1.y = fmaxf(v1.y, 0.f);
                v1.z = fmaxf(v1.z, 0.f); v1.w = fmaxf(v1.w, 0.f);
            }
            xa[4*cc+0] = f2pack(v0.x, v0.x); xa[4*cc+1] = f2pack(v0.y, v0.y);
            xa[4*cc+2] = f2pack(v0.z, v0.z); xa[4*cc+3] = f2pack(v0.w, v0.w);
            xb[4*cc+0] = f2pack(v1.x, v1.x); xb[4*cc+1] = f2pack(v1.y, v1.y);
            xb[4*cc+2] = f2pack(v1.z, v1.z); xb[4*cc+3] = f2pack(v1.w, v1.w);
        }
    }

    float4* Zo0 = g_Z4 + (size_t)n0 * 20;
    float4* Zo1 = g_Z4 + (size_t)n1 * 20;
    const int d0 = r ? 5 : 0;
    const int d1 = r ? 9 : 5;
    #pragma unroll 1
    for (int d = d0; d < d1; d++) {
        const ulonglong2* Wd = (const ulonglong2*)(sWB + d * 64);
        __half2 ha[8], hb[8];
        #pragma unroll
        for (int oc = 0; oc < 4; oc++) {
            unsigned long long a0 = 0ull, a1 = 0ull;
            unsigned long long b0 = 0ull, b1 = 0ull;
            #pragma unroll
            for (int i = 0; i < 16; i++) {
                ulonglong2 w = Wd[i * 4 + oc];
                a0 = ffma2(xa[i], w.x, a0);
                a1 = ffma2(xa[i], w.y, a1);
                b0 = ffma2(xb[i], w.x, b0);
                b1 = ffma2(xb[i], w.y, b1);
            }
            float f0, f1, f2, f3;
            f2unpack(a0, f0, f1); f2unpack(a1, f2, f3);
            ha[2*oc+0] = __floats2half2_rn(f0, f1);
            ha[2*oc+1] = __floats2half2_rn(f2, f3);
            f2unpack(b0, f0, f1); f2unpack(b1, f2, f3);
            hb[2*oc+0] = __floats2half2_rn(f0, f1);
            hb[2*oc+1] = __floats2half2_rn(f2, f3);
        }
        Zo0[d * 2 + 0] = *(float4*)&ha[0];
        Zo0[d * 2 + 1] = *(float4*)&ha[4];
        Zo1[d * 2 + 0] = *(float4*)&hb[0];
        Zo1[d * 2 + 1] = *(float4*)&hb[4];
    }

    if (r) {
        const ulonglong2* Rd = (const ulonglong2*)sR;
        float4* Ao0 = (float4*)(aggOut + (size_t)n0 * 16);
        float4* Ao1 = (float4*)(aggOut + (size_t)n1 * 16);
        #pragma unroll
        for (int oc = 0; oc < 4; oc++) {
            float4 bi = sBias[oc];
            unsigned long long a0 = f2pack(bi.x, bi.y);
            unsigned long long a1 = f2pack(bi.z, bi.w);
            unsigned long long b0 = a0, b1 = a1;
            #pragma unroll
            for (int i = 0; i < 16; i++) {
                ulonglong2 w = Rd[i * 4 + oc];
                a0 = ffma2(xa[i], w.x, a0);
                a1 = ffma2(xa[i], w.y, a1);
                b0 = ffma2(xb[i], w.x, b0);
                b1 = ffma2(xb[i], w.y, b1);
            }
            float4 o;
            f2unpack(a0, o.x, o.y); f2unpack(a1, o.z, o.w);
            Ao0[oc] = o;
            f2unpack(b0, o.x, o.y); f2unpack(b1, o.z, o.w);
            Ao1[oc] = o;
        }
    }
}

// ---------------------------------------------------------------------------
// fused0: blocks [0,196) = prep layer 0; blocks [196, 196+3125) = bucket
// histogram over edges (g_cnt zero on entry by invariant). Independent work
// classes overlap: hist's atomics stream under prep0's latency bubbles.
// ---------------------------------------------------------------------------
__global__ void __launch_bounds__(256) fused0_kernel(
    const float* __restrict__ x, const int* __restrict__ ei,
    const float* __restrict__ nnW, const float* __restrict__ nnb,
    const float* __restrict__ rootW, const float* __restrict__ bias)
{
    if (blockIdx.x >= PREP0_BLOCKS) {
        const int e = (blockIdx.x - PREP0_BLOCKS) * 256 + threadIdx.x;
        if (e < NE) atomicAdd(&g_cnt[ei[e] >> 4], 1);
        return;
    }

    __shared__ float4 sWB[576];
    __shared__ float4 sR[64];
    __shared__ float4 sBias[4];

    const int tid = threadIdx.x;
    {
        const float4* W4  = (const float4*)nnW;
        const float4* B4  = (const float4*)nnb;
        const float4* R4  = (const float4*)rootW;
        const float4* Bi4 = (const float4*)bias;
        #pragma unroll
        for (int j = tid; j < 512; j += 256) sWB[j] = W4[j];
        if (tid < 64) { sWB[512 + tid] = B4[tid]; sR[tid] = R4[tid]; }
        if (tid < 4)  sBias[tid] = Bi4[tid];
    }
    __syncthreads();

    const int warp = tid >> 5;
    const int lane = tid & 31;
    const int p    = blockIdx.x * 128 + (warp >> 1) * 32 + lane;
    if (p >= HN) return;
    prep_pair(x, p, p + HN, warp & 1, false, sWB, sR, sBias, g_agg[0]);
}

// ---------------------------------------------------------------------------
// scan: ONE 1024-thread block scans the 3125 bucket counts into exclusive
// cursors (g_cur) and RE-ZEROES g_cnt (restores the launch invariant).
// Thread t owns buckets [4t, 4t+4).
// ---------------------------------------------------------------------------
__global__ void __launch_bounds__(1024) scan_kernel()
{
    const int t    = threadIdx.x;
    const int lane = t & 31;
    const int wid  = t >> 5;
    const int base = t * 4;

    int v[4];
    int s = 0;
    #pragma unroll
    for (int i = 0; i < 4; i++) {
        const int idx = base + i;
        v[i] = (idx < NB) ? g_cnt[idx] : 0;
        s += v[i];
    }

    int ps = s;
    #pragma unroll
    for (int o = 1; o < 32; o <<= 1) {
        int y = __shfl_up_sync(0xffffffffu, ps, o);
        if (lane >= o) ps += y;
    }
    __shared__ int ws[32];
    if (lane == 31) ws[wid] = ps;
    __syncthreads();
    if (t < 32) {
        int w = ws[t];
        #pragma unroll
        for (int o = 1; o < 32; o <<= 1) {
            int y = __shfl_up_sync(0xffffffffu, w, o);
            if (t >= o) w += y;
        }
        ws[t] = w;
    }
    __syncthreads();

    int run = ps - s + (wid ? ws[wid - 1] : 0);   // exclusive prefix of thread
    #pragma unroll
    for (int i = 0; i < 4; i++) {
        const int idx = base + i;
        if (idx < NB) {
            g_cur[idx] = run;
            run += v[i];
            g_cnt[idx] = 0;   // restore invariant for next launch
        }
    }
}

// ---------------------------------------------------------------------------
// scatter: place each edge into its src-bucket run; pack fp16 coeffs inline.
// ---------------------------------------------------------------------------
__global__ void __launch_bounds__(256) scatter_kernel(
    const int* __restrict__ ei, const float* __restrict__ ea)
{
    const int e = blockIdx.x * 256 + threadIdx.x;
    if (e >= NE) return;
    const int src = ei[e];
    const int dst = ei[NE + e];
    const int pos = atomicAdd(&g_cur[src >> 4], 1);

    const float4 a = ((const float4*)ea)[(size_t)e * 2 + 0];  // c0..c3
    const float4 b = ((const float4*)ea)[(size_t)e * 2 + 1];  // c4..c7
    __half2 h0[4] = { __float2half2_rn(a.x), __float2half2_rn(a.z),
                      __float2half2_rn(b.x), __float2half2_rn(b.z) };
    __half2 h1[4] = { __float2half2_rn(a.y), __float2half2_rn(a.w),
                      __float2half2_rn(b.y), __float2half2_rn(b.w) };
    g_spc[(size_t)pos * 2 + 0] = *(float4*)h0;
    g_spc[(size_t)pos * 2 + 1] = *(float4*)h1;
    g_sidx[pos] = make_int2(src, dst);
}

// ---------------------------------------------------------------------------
// prep (layers 1,2): warp-uniform d-split, 2 nodes/thread (best measured).
// ---------------------------------------------------------------------------
__global__ void __launch_bounds__(128) prep_kernel(
    int layer,
    const float* __restrict__ nnW, const float* __restrict__ nnb,
    const float* __restrict__ rootW, const float* __restrict__ bias)
{
    __shared__ float4 sWB[576];
    __shared__ float4 sR[64];
    __shared__ float4 sBias[4];

    const int tid = threadIdx.x;
    {
        const float4* W4  = (const float4*)(nnW   + (size_t)layer * 2048);
        const float4* B4  = (const float4*)(nnb   + (size_t)layer * 256);
        const float4* R4  = (const float4*)(rootW + (size_t)layer * 256);
        const float4* Bi4 = (const float4*)(bias  + (size_t)layer * 16);
        #pragma unroll
        for (int j = tid; j < 512; j += 128) sWB[j] = W4[j];
        for (int j = tid; j < 64;  j += 128) { sWB[512 + j] = B4[j]; sR[j] = R4[j]; }
        if (tid < 4) sBias[tid] = Bi4[tid];
    }
    __syncthreads();

    const int warp = tid >> 5;
    const int lane = tid & 31;
    const int p    = blockIdx.x * 64 + (warp >> 1) * 32 + lane;
    if (p >= HN) return;
    prep_pair(g_agg[(layer - 1) & 1], p, p + HN, warp & 1, true,
              sWB, sR, sBias, g_agg[layer & 1]);
}

// ---------------------------------------------------------------------------
// edge: 4 threads per edge over the bucket-sorted edge array. A 64-edge
// block touches <=16 nodes' Z (5KB, L1-resident) -> gather is L1 hits.
// ---------------------------------------------------------------------------
__global__ void __launch_bounds__(256) edge_kernel(int layer)
{
    const int gid = blockIdx.x * 256 + threadIdx.x;
    const int e   = gid >> 2;
    const int q   = gid & 3;
    const int hi  = q >> 1;

    const int2 sd = g_sidx[e];
    const float4 cpack = g_spc[(size_t)e * 2 + hi];
    const __half2* cp = (const __half2*)&cpack;
    const __half2 c0 = cp[0], c1 = cp[1], c2 = cp[2], c3 = cp[3];

    const float4* zp = g_Z4 + (size_t)sd.x * 20 + q;
    float4 v0 = *(zp + 0);     // L1-cached: bucketed srcs give heavy reuse
    float4 v1 = *(zp + 4);
    float4 v2 = *(zp + 8);
    float4 v3 = *(zp + 12);

    const __half2* h0 = (const __half2*)&v0;
    const __half2* h1 = (const __half2*)&v1;
    const __half2* h2 = (const __half2*)&v2;
    const __half2* h3 = (const __half2*)&v3;

    float m[8];
    #pragma unroll
    for (int j = 0; j < 4; j++) {
        __half2 t1 = __hfma2(c1, h1[j], __hmul2(c0, h0[j]));
        __half2 t2 = __hfma2(c3, h3[j], __hmul2(c2, h2[j]));
        float2 f1 = __half22float2(t1);
        float2 f2 = __half22float2(t2);
        m[2*j]   = f1.x + f2.x;
        m[2*j+1] = f1.y + f2.y;
    }

    if (q < 2) {  // nnb term (d=8, coefficient 1), added in fp32
        float4 vb = *(zp + 16);
        const __half2* hb = (const __half2*)&vb;
        #pragma unroll
        for (int j = 0; j < 4; j++) {
            float2 t = __half22float2(hb[j]);
            m[2*j] += t.x; m[2*j+1] += t.y;
        }
    }

    float r[4];
    #pragma unroll
    for (int i = 0; i < 4; i++) {
        float send = hi ? m[i] : m[4 + i];
        float recv = __shfl_xor_sync(0xffffffffu, send, 2);
        r[i] = m[hi * 4 + i] + recv;
    }

    float* ag = g_agg[layer & 1] + (size_t)sd.y * 16 + (q & 1) * 8 + hi * 4;
    asm volatile("red.global.add.v4.f32 [%0], {%1,%2,%3,%4};"
                 :: "l"(ag), "f"(r[0]), "f"(r[1]), "f"(r[2]), "f"(r[3]) : "memory");
}

// ---------------------------------------------------------------------------
// head: out[n] = relu(agg[n]) . head_W[0:16] + gf[:,n] . head_W[16:24] + head_b
// ---------------------------------------------------------------------------
__global__ void __launch_bounds__(256) head_kernel(
    const float* __restrict__ gf, const float* __restrict__ hW,
    const float* __restrict__ hb, float* __restrict__ out)
{
    const int n = blockIdx.x * 256 + threadIdx.x;
    if (n >= NN) return;

    const float4* ar = (const float4*)(g_agg[0] + (size_t)n * 16);  // layer 2 wrote buf 0
    float acc = hb[0];
    #pragma unroll
    for (int c = 0; c < 4; c++) {
        float4 v = ar[c];
        acc = fmaf(fmaxf(v.x, 0.f), hW[4*c+0], acc);
        acc = fmaf(fmaxf(v.y, 0.f), hW[4*c+1], acc);
        acc = fmaf(fmaxf(v.z, 0.f), hW[4*c+2], acc);
        acc = fmaf(fmaxf(v.w, 0.f), hW[4*c+3], acc);
    }
    #pragma unroll
    for (int g = 0; g < 8; g++)
        acc = fmaf(gf[(size_t)g * NN + n], hW[16 + g], acc);
    out[n] = acc;
}

extern "C" void kernel_launch(void* const* d_in, const int* in_sizes, int n_in,
                              void* d_out, int out_size)
{
    const float* x     = (const float*)d_in[0];
    const int*   ei    = (const int*)  d_in[1];
    const float* ea    = (const float*)d_in[2];
    const float* gf    = (const float*)d_in[3];
    const float* nnW   = (const float*)d_in[4];
    const float* nnb   = (const float*)d_in[5];
    const float* rootW = (const float*)d_in[6];
    const float* bias  = (const float*)d_in[7];
    const float* hW    = (const float*)d_in[8];
    const float* hb    = (const float*)d_in[9];
    float* out = (float*)d_out;

    fused0_kernel<<<PREP0_BLOCKS + HIST_BLOCKS, 256>>>(x, ei, nnW, nnb, rootW, bias);
    scan_kernel<<<1, 1024>>>();
    scatter_kernel<<<(NE + 255) / 256, 256>>>(ei, ea);

    edge_kernel<<<NE * 4 / 256, 256>>>(0);
    prep_kernel<<<(HN + 63) / 64, 128>>>(1, nnW, nnb, rootW, bias);
    edge_kernel<<<NE * 4 / 256, 256>>>(1);
    prep_kernel<<<(HN + 63) / 64, 128>>>(2, nnW, nnb, rootW, bias);
    edge_kernel<<<NE * 4 / 256, 256>>>(2);
    head_kernel<<<(NN + 255) / 256, 256>>>(gf, hW, hb, out);
}

// round 17
// speedup vs baseline: 1.2149x; 1.2149x over previous
#include <cuda_runtime.h>
#include <cuda_fp16.h>

#define NN 50000
#define NE 800000
#define HN 25000           // node pairs: pair p handles nodes p and p+HN
#define PREP_BLOCKS 391    // ceil(25000/64) pairs, 64 pairs per 128-thr block
#define PACK_BLOCKS 6250   // 800000/128
// dynamic smem: sWB[576] | sR[64] | sBias[4] | sZ[128*21]  (float4 units)
#define SM_WB 0
#define SM_R 576
#define SM_BIAS 640
#define SM_Z 644
#define SMEM_F4 (644 + 128 * 21)
#define SMEM_BYTES (SMEM_F4 * 16)

// Scratch (device globals — no allocation allowed in kernel_launch).
__device__ float4 g_Z4[(size_t)NN * 20];      // per-node Z, fp16, 320B stride
__device__ float  g_agg[2][(size_t)NN * 16];  // ping-pong node feature buffers
__device__ float4 g_pc[(size_t)NE * 2];       // packed broadcast fp16 coeffs
__device__ int2   g_idx[(size_t)NE];          // (src, dst)

// ---- packed f32x2 helpers (FFMA2: 2 fp32 FMAs per instruction, exact) ----
__device__ __forceinline__ unsigned long long f2pack(float lo, float hi) {
    unsigned long long d;
    asm("mov.b64 %0, {%1, %2};" : "=l"(d) : "f"(lo), "f"(hi));
    return d;
}
__device__ __forceinline__ void f2unpack(unsigned long long v, float& lo, float& hi) {
    asm("mov.b64 {%0, %1}, %2;" : "=f"(lo), "=f"(hi) : "l"(v));
}
__device__ __forceinline__ unsigned long long ffma2(
    unsigned long long a, unsigned long long b, unsigned long long c) {
    unsigned long long d;
    asm("fma.rn.f32x2 %0, %1, %2, %3;" : "=l"(d) : "l"(a), "l"(b), "l"(c));
    return d;
}

// ---------------------------------------------------------------------------
// Core prep body for one 128-thread block covering 64 pairs.
// Warp-uniform roles (warp w: pair-group pg=w>>1, role r=w&1).
// Z written to smem tile sZ (node-local stride 21 quads, conflict-free STS),
// then flushed coalesced to g_Z4 — kills the 32-wf/instr scattered stores.
// ---------------------------------------------------------------------------
__device__ __forceinline__ void prep_block(
    const float* __restrict__ xin, bool relu, float* __restrict__ aggOut,
    int blockBase /* first pair of block */, float4* sm)
{
    float4* sWB   = sm + SM_WB;
    float4* sR    = sm + SM_R;
    float4* sBias = sm + SM_BIAS;
    float4* sZ    = sm + SM_Z;

    const int tid  = threadIdx.x;
    const int warp = tid >> 5;
    const int lane = tid & 31;
    const int pg   = warp >> 1;
    const int r    = warp & 1;
    const int nloc0 = pg * 32 + lane;      // 0..63 (pair-local)
    const int p     = blockBase + nloc0;
    const bool live = (p < HN);

    if (live) {
        const int n0 = p;
        const int n1 = p + HN;

        unsigned long long xa[16], xb[16];
        {
            const float4* xr0 = (const float4*)(xin + (size_t)n0 * 16);
            const float4* xr1 = (const float4*)(xin + (size_t)n1 * 16);
            #pragma unroll
            for (int cc = 0; cc < 4; cc++) {
                float4 v0 = xr0[cc];
                float4 v1 = xr1[cc];
                if (relu) {
                    v0.x = fmaxf(v0.x, 0.f); v0.y = fmaxf(v0.y, 0.f);
                    v0.z = fmaxf(v0.z, 0.f); v0.w = fmaxf(v0.w, 0.f);
                    v1.x = fmaxf(v1.x, 0.f); v1.y = fmaxf(v1.y, 0.f);
                    v1.z = fmaxf(v1.z, 0.f); v1.w = fmaxf(v1.w, 0.f);
                }
                xa[4*cc+0] = f2pack(v0.x, v0.x); xa[4*cc+1] = f2pack(v0.y, v0.y);
                xa[4*cc+2] = f2pack(v0.z, v0.z); xa[4*cc+3] = f2pack(v0.w, v0.w);
                xb[4*cc+0] = f2pack(v1.x, v1.x); xb[4*cc+1] = f2pack(v1.y, v1.y);
                xb[4*cc+2] = f2pack(v1.z, v1.z); xb[4*cc+3] = f2pack(v1.w, v1.w);
            }
        }

        float4* Zs0 = sZ + nloc0 * 21;
        float4* Zs1 = sZ + (64 + nloc0) * 21;
        const int d0 = r ? 5 : 0;
        const int d1 = r ? 9 : 5;
        #pragma unroll 1
        for (int d = d0; d < d1; d++) {
            const ulonglong2* Wd = (const ulonglong2*)(sWB + d * 64);
            __half2 ha[8], hb[8];
            #pragma unroll
            for (int oc = 0; oc < 4; oc++) {
                unsigned long long a0 = 0ull, a1 = 0ull;
                unsigned long long b0 = 0ull, b1 = 0ull;
                #pragma unroll
                for (int i = 0; i < 16; i++) {
                    ulonglong2 w = Wd[i * 4 + oc];
                    a0 = ffma2(xa[i], w.x, a0);
                    a1 = ffma2(xa[i], w.y, a1);
                    b0 = ffma2(xb[i], w.x, b0);
                    b1 = ffma2(xb[i], w.y, b1);
                }
                float f0, f1, f2, f3;
                f2unpack(a0, f0, f1); f2unpack(a1, f2, f3);
                ha[2*oc+0] = __floats2half2_rn(f0, f1);
                ha[2*oc+1] = __floats2half2_rn(f2, f3);
                f2unpack(b0, f0, f1); f2unpack(b1, f2, f3);
                hb[2*oc+0] = __floats2half2_rn(f0, f1);
                hb[2*oc+1] = __floats2half2_rn(f2, f3);
            }
            Zs0[d * 2 + 0] = *(float4*)&ha[0];
            Zs0[d * 2 + 1] = *(float4*)&ha[4];
            Zs1[d * 2 + 0] = *(float4*)&hb[0];
            Zs1[d * 2 + 1] = *(float4*)&hb[4];
        }

        if (r) {  // root term: direct store (only 4 instr; leave unstaged)
            const ulonglong2* Rd = (const ulonglong2*)sR;
            float4* Ao0 = (float4*)(aggOut + (size_t)n0 * 16);
            float4* Ao1 = (float4*)(aggOut + (size_t)n1 * 16);
            #pragma unroll
            for (int oc = 0; oc < 4; oc++) {
                float4 bi = sBias[oc];
                unsigned long long a0 = f2pack(bi.x, bi.y);
                unsigned long long a1 = f2pack(bi.z, bi.w);
                unsigned long long b0 = a0, b1 = a1;
                #pragma unroll
                for (int i = 0; i < 16; i++) {
                    ulonglong2 w = Rd[i * 4 + oc];
                    a0 = ffma2(xa[i], w.x, a0);
                    a1 = ffma2(xa[i], w.y, a1);
                    b0 = ffma2(xb[i], w.x, b0);
                    b1 = ffma2(xb[i], w.y, b1);
                }
                float4 o;
                f2unpack(a0, o.x, o.y); f2unpack(a1, o.z, o.w);
                Ao0[oc] = o;
                f2unpack(b0, o.x, o.y); f2unpack(b1, o.z, o.w);
                Ao1[oc] = o;
            }
        }
    }

    __syncthreads();

    // Coalesced flush: chunk c=0 -> nodes blockBase.., c=1 -> +HN.
    // j enumerates (node-local, f<18); guard skips pairs >= HN.
    #pragma unroll 1
    for (int c = 0; c < 2; c++) {
        const size_t gbase = ((size_t)blockBase + (size_t)c * HN) * 20;
        #pragma unroll 1
        for (int j = tid; j < 64 * 18; j += 128) {
            const int nl = j / 18;
            const int f  = j - nl * 18;
            if (blockBase + nl < HN)
                g_Z4[gbase + (size_t)nl * 20 + f] = sZ[(c * 64 + nl) * 21 + f];
        }
    }
}

__device__ __forceinline__ void prep_stage_weights(
    int layer, const float* nnW, const float* nnb,
    const float* rootW, const float* bias, float4* sm)
{
    const int tid = threadIdx.x;
    const float4* W4  = (const float4*)(nnW   + (size_t)layer * 2048);
    const float4* B4  = (const float4*)(nnb   + (size_t)layer * 256);
    const float4* R4  = (const float4*)(rootW + (size_t)layer * 256);
    const float4* Bi4 = (const float4*)(bias  + (size_t)layer * 16);
    #pragma unroll
    for (int j = tid; j < 512; j += 128) sm[SM_WB + j] = W4[j];
    for (int j = tid; j < 64;  j += 128) { sm[SM_WB + 512 + j] = B4[j]; sm[SM_R + j] = R4[j]; }
    if (tid < 4) sm[SM_BIAS + tid] = Bi4[tid];
    __syncthreads();
}

// ---------------------------------------------------------------------------
// fused0: blocks [0,391) = prep layer 0 (smem-staged); rest = edge pack.
// ---------------------------------------------------------------------------
__global__ void __launch_bounds__(128) fused0_kernel(
    const float* __restrict__ x, const int* __restrict__ ei,
    const float* __restrict__ ea,
    const float* __restrict__ nnW, const float* __restrict__ nnb,
    const float* __restrict__ rootW, const float* __restrict__ bias)
{
    if (blockIdx.x >= PREP_BLOCKS) {
        const int e = (blockIdx.x - PREP_BLOCKS) * 128 + threadIdx.x;
        if (e >= NE) return;
        const float4 a = ((const float4*)ea)[(size_t)e * 2 + 0];  // c0..c3
        const float4 b = ((const float4*)ea)[(size_t)e * 2 + 1];  // c4..c7
        __half2 h0[4] = { __float2half2_rn(a.x), __float2half2_rn(a.z),
                          __float2half2_rn(b.x), __float2half2_rn(b.z) };
        __half2 h1[4] = { __float2half2_rn(a.y), __float2half2_rn(a.w),
                          __float2half2_rn(b.y), __float2half2_rn(b.w) };
        g_pc[(size_t)e * 2 + 0] = *(float4*)h0;
        g_pc[(size_t)e * 2 + 1] = *(float4*)h1;
        g_idx[e] = make_int2(ei[e], ei[NE + e]);
        return;
    }

    extern __shared__ float4 sm[];
    prep_stage_weights(0, nnW, nnb, rootW, bias, sm);
    prep_block(x, false, g_agg[0], blockIdx.x * 64, sm);
}

// ---------------------------------------------------------------------------
// prep (layers 1,2)
// ---------------------------------------------------------------------------
__global__ void __launch_bounds__(128) prep_kernel(
    int layer,
    const float* __restrict__ nnW, const float* __restrict__ nnb,
    const float* __restrict__ rootW, const float* __restrict__ bias)
{
    extern __shared__ float4 sm[];
    prep_stage_weights(layer, nnW, nnb, rootW, bias, sm);
    prep_block(g_agg[(layer - 1) & 1], true, g_agg[layer & 1],
               blockIdx.x * 64, sm);
}

// ---------------------------------------------------------------------------
// edge: 4 threads per edge (best measured config, R14 verbatim).
// ---------------------------------------------------------------------------
__global__ void __launch_bounds__(256) edge_kernel(int layer)
{
    const int gid = blockIdx.x * 256 + threadIdx.x;
    const int e   = gid >> 2;
    const int q   = gid & 3;
    const int hi  = q >> 1;

    const int2 sd = g_idx[e];
    const float4 cpack = g_pc[(size_t)e * 2 + hi];
    const __half2* cp = (const __half2*)&cpack;
    const __half2 c0 = cp[0], c1 = cp[1], c2 = cp[2], c3 = cp[3];

    const float4* zp = g_Z4 + (size_t)sd.x * 20 + q;
    float4 v0 = __ldcg(zp + 0);
    float4 v1 = __ldcg(zp + 4);
    float4 v2 = __ldcg(zp + 8);
    float4 v3 = __ldcg(zp + 12);

    const __half2* h0 = (const __half2*)&v0;
    const __half2* h1 = (const __half2*)&v1;
    const __half2* h2 = (const __half2*)&v2;
    const __half2* h3 = (const __half2*)&v3;

    float m[8];
    #pragma unroll
    for (int j = 0; j < 4; j++) {
        __half2 t1 = __hfma2(c1, h1[j], __hmul2(c0, h0[j]));
        __half2 t2 = __hfma2(c3, h3[j], __hmul2(c2, h2[j]));
        float2 f1 = __half22float2(t1);
        float2 f2 = __half22float2(t2);
        m[2*j]   = f1.x + f2.x;
        m[2*j+1] = f1.y + f2.y;
    }

    if (q < 2) {  // nnb term (d=8, coefficient 1), added in fp32
        float4 vb = __ldcg(zp + 16);
        const __half2* hb = (const __half2*)&vb;
        #pragma unroll
        for (int j = 0; j < 4; j++) {
            float2 t = __half22float2(hb[j]);
            m[2*j] += t.x; m[2*j+1] += t.y;
        }
    }

    float r[4];
    #pragma unroll
    for (int i = 0; i < 4; i++) {
        float send = hi ? m[i] : m[4 + i];
        float recv = __shfl_xor_sync(0xffffffffu, send, 2);
        r[i] = m[hi * 4 + i] + recv;
    }

    float* ag = g_agg[layer & 1] + (size_t)sd.y * 16 + (q & 1) * 8 + hi * 4;
    asm volatile("red.global.add.v4.f32 [%0], {%1,%2,%3,%4};"
                 :: "l"(ag), "f"(r[0]), "f"(r[1]), "f"(r[2]), "f"(r[3]) : "memory");
}

// ---------------------------------------------------------------------------
// head
// ---------------------------------------------------------------------------
__global__ void __launch_bounds__(256) head_kernel(
    const float* __restrict__ gf, const float* __restrict__ hW,
    const float* __restrict__ hb, float* __restrict__ out)
{
    const int n = blockIdx.x * 256 + threadIdx.x;
    if (n >= NN) return;

    const float4* ar = (const float4*)(g_agg[0] + (size_t)n * 16);  // layer 2 wrote buf 0
    float acc = hb[0];
    #pragma unroll
    for (int c = 0; c < 4; c++) {
        float4 v = ar[c];
        acc = fmaf(fmaxf(v.x, 0.f), hW[4*c+0], acc);
        acc = fmaf(fmaxf(v.y, 0.f), hW[4*c+1], acc);
        acc = fmaf(fmaxf(v.z, 0.f), hW[4*c+2], acc);
        acc = fmaf(fmaxf(v.w, 0.f), hW[4*c+3], acc);
    }
    #pragma unroll
    for (int g = 0; g < 8; g++)
        acc = fmaf(gf[(size_t)g * NN + n], hW[16 + g], acc);
    out[n] = acc;
}

extern "C" void kernel_launch(void* const* d_in, const int* in_sizes, int n_in,
                              void* d_out, int out_size)
{
    const float* x     = (const float*)d_in[0];
    const int*   ei    = (const int*)  d_in[1];
    const float* ea    = (const float*)d_in[2];
    const float* gf    = (const float*)d_in[3];
    const float* nnW   = (const float*)d_in[4];
    const float* nnb   = (const float*)d_in[5];
    const float* rootW = (const float*)d_in[6];
    const float* bias  = (const float*)d_in[7];
    const float* hW    = (const float*)d_in[8];
    const float* hb    = (const float*)d_in[9];
    float* out = (float*)d_out;

    cudaFuncSetAttribute(fused0_kernel,
        cudaFuncAttributeMaxDynamicSharedMemorySize, SMEM_BYTES);
    cudaFuncSetAttribute(prep_kernel,
        cudaFuncAttributeMaxDynamicSharedMemorySize, SMEM_BYTES);

    fused0_kernel<<<PREP_BLOCKS + PACK_BLOCKS, 128, SMEM_BYTES>>>(
        x, ei, ea, nnW, nnb, rootW, bias);
    edge_kernel<<<NE * 4 / 256, 256>>>(0);
    prep_kernel<<<PREP_BLOCKS, 128, SMEM_BYTES>>>(1, nnW, nnb, rootW, bias);
    edge_kernel<<<NE * 4 / 256, 256>>>(1);
    prep_kernel<<<PREP_BLOCKS, 128, SMEM_BYTES>>>(2, nnW, nnb, rootW, bias);
    edge_kernel<<<NE * 4 / 256, 256>>>(2);
    head_kernel<<<(NN + 255) / 256, 256>>>(gf, hW, hb, out);
}